// round 2
// baseline (speedup 1.0000x reference)
#include <cuda_runtime.h>
#include <math.h>

#define ENC 1024
#define PRED 320
#define JH 512
#define VOCAB 29
#define BLANK 28
#define MAXSYM 6
#define BATCH 32
#define TLEN 48
#define NSTEPS (TLEN * MAXSYM)   // 288
#define ZDIM (ENC + PRED)        // 1344

__device__ __forceinline__ float sigf(float v) { return 1.0f / (1.0f + expf(-v)); }

__global__ __launch_bounds__(1024, 1)
void rnnt_greedy_kernel(const float* __restrict__ x,
                        const int*   __restrict__ out_lens,
                        const float* __restrict__ emb,
                        const float* __restrict__ Wi0, const float* __restrict__ Wh0, const float* __restrict__ b0,
                        const float* __restrict__ Wi1, const float* __restrict__ Wh1, const float* __restrict__ b1,
                        const float* __restrict__ Wj1, const float* __restrict__ bj1,
                        const float* __restrict__ Wj2, const float* __restrict__ bj2,
                        float* __restrict__ d_out, int write_lc)
{
    const int b    = blockIdx.x;
    const int tid  = threadIdx.x;
    const int lane = tid & 31;
    const int warp = tid >> 5;

    __shared__ __align__(16) float sh_h0[PRED],  sh_c0[PRED],  sh_h1[PRED],  sh_c1[PRED];
    __shared__ __align__(16) float sh_h0p[PRED], sh_c0p[PRED], sh_h1p[PRED], sh_c1p[PRED];
    __shared__ __align__(16) float sh_e[PRED];
    __shared__ __align__(16) float sh_f[ENC];
    __shared__ __align__(16) float sh_g[4 * PRED];
    __shared__ __align__(16) float sh_hid[JH];
    __shared__ __align__(16) float sh_logit[VOCAB];
    __shared__ int sh_lt[NSTEPS];
    __shared__ int s_last, s_lc, s_ti, s_sa, s_nb;

    // init lt row to -1, state to zero
    for (int i = tid; i < NSTEPS; i += 1024) sh_lt[i] = -1;
    if (tid < PRED) { sh_h0[tid] = 0.f; sh_c0[tid] = 0.f; sh_h1[tid] = 0.f; sh_c1[tid] = 0.f; }
    if (tid == 0) { s_last = -1; s_lc = 0; s_ti = 0; s_sa = 0; s_nb = 0; }
    __syncthreads();

    const int olen = out_lens[b];

    for (int step = 0; step < NSTEPS; ++step) {
        // ---- P0: encoder frame f = x[b, min(ti, T-1)], embedding e ----
        {
            int fi = s_ti; if (fi > TLEN - 1) fi = TLEN - 1;
            sh_f[tid] = x[(b * TLEN + fi) * ENC + tid];
            if (tid < PRED) {
                int lab = s_last;
                if (lab > VOCAB - 2) lab = VOCAB - 2;   // JAX gather clamp
                sh_e[tid] = (s_last >= 0) ? emb[lab * PRED + tid] : 0.0f;
            }
        }
        __syncthreads();

        // ---- P1: gates0 = e @ Wi0^T + h0 @ Wh0^T + b0  (1280 rows, 40/warp) ----
        {
            float4 e4a = *(const float4*)&sh_e[4 * lane];
            float4 e4b = *(const float4*)&sh_e[128 + 4 * lane];
            float2 e2  = *(const float2*)&sh_e[256 + 2 * lane];
            float4 h4a = *(const float4*)&sh_h0[4 * lane];
            float4 h4b = *(const float4*)&sh_h0[128 + 4 * lane];
            float2 h2  = *(const float2*)&sh_h0[256 + 2 * lane];
            int rbase = warp * 40;
            for (int rr = 0; rr < 40; ++rr) {
                int r = rbase + rr;
                const float* wi = Wi0 + r * PRED;
                const float* wh = Wh0 + r * PRED;
                float4 w;
                float acc = 0.f;
                w = *(const float4*)&wi[4 * lane];
                acc = fmaf(w.x, e4a.x, acc); acc = fmaf(w.y, e4a.y, acc);
                acc = fmaf(w.z, e4a.z, acc); acc = fmaf(w.w, e4a.w, acc);
                w = *(const float4*)&wi[128 + 4 * lane];
                acc = fmaf(w.x, e4b.x, acc); acc = fmaf(w.y, e4b.y, acc);
                acc = fmaf(w.z, e4b.z, acc); acc = fmaf(w.w, e4b.w, acc);
                {   float2 w2 = *(const float2*)&wi[256 + 2 * lane];
                    acc = fmaf(w2.x, e2.x, acc); acc = fmaf(w2.y, e2.y, acc); }
                w = *(const float4*)&wh[4 * lane];
                acc = fmaf(w.x, h4a.x, acc); acc = fmaf(w.y, h4a.y, acc);
                acc = fmaf(w.z, h4a.z, acc); acc = fmaf(w.w, h4a.w, acc);
                w = *(const float4*)&wh[128 + 4 * lane];
                acc = fmaf(w.x, h4b.x, acc); acc = fmaf(w.y, h4b.y, acc);
                acc = fmaf(w.z, h4b.z, acc); acc = fmaf(w.w, h4b.w, acc);
                {   float2 w2 = *(const float2*)&wh[256 + 2 * lane];
                    acc = fmaf(w2.x, h2.x, acc); acc = fmaf(w2.y, h2.y, acc); }
                #pragma unroll
                for (int o = 16; o > 0; o >>= 1) acc += __shfl_down_sync(0xffffffffu, acc, o);
                if (lane == 0) sh_g[r] = acc + b0[r];
            }
        }
        __syncthreads();

        // ---- P2: LSTM0 nonlinearity ----
        if (tid < PRED) {
            float gi = sh_g[tid], gf = sh_g[PRED + tid], gg = sh_g[2 * PRED + tid], go = sh_g[3 * PRED + tid];
            float c = sigf(gf) * sh_c0[tid] + sigf(gi) * tanhf(gg);
            sh_c0p[tid] = c;
            sh_h0p[tid] = sigf(go) * tanhf(c);
        }
        __syncthreads();

        // ---- P3: gates1 = h0p @ Wi1^T + h1 @ Wh1^T + b1 ----
        {
            float4 e4a = *(const float4*)&sh_h0p[4 * lane];
            float4 e4b = *(const float4*)&sh_h0p[128 + 4 * lane];
            float2 e2  = *(const float2*)&sh_h0p[256 + 2 * lane];
            float4 h4a = *(const float4*)&sh_h1[4 * lane];
            float4 h4b = *(const float4*)&sh_h1[128 + 4 * lane];
            float2 h2  = *(const float2*)&sh_h1[256 + 2 * lane];
            int rbase = warp * 40;
            for (int rr = 0; rr < 40; ++rr) {
                int r = rbase + rr;
                const float* wi = Wi1 + r * PRED;
                const float* wh = Wh1 + r * PRED;
                float4 w;
                float acc = 0.f;
                w = *(const float4*)&wi[4 * lane];
                acc = fmaf(w.x, e4a.x, acc); acc = fmaf(w.y, e4a.y, acc);
                acc = fmaf(w.z, e4a.z, acc); acc = fmaf(w.w, e4a.w, acc);
                w = *(const float4*)&wi[128 + 4 * lane];
                acc = fmaf(w.x, e4b.x, acc); acc = fmaf(w.y, e4b.y, acc);
                acc = fmaf(w.z, e4b.z, acc); acc = fmaf(w.w, e4b.w, acc);
                {   float2 w2 = *(const float2*)&wi[256 + 2 * lane];
                    acc = fmaf(w2.x, e2.x, acc); acc = fmaf(w2.y, e2.y, acc); }
                w = *(const float4*)&wh[4 * lane];
                acc = fmaf(w.x, h4a.x, acc); acc = fmaf(w.y, h4a.y, acc);
                acc = fmaf(w.z, h4a.z, acc); acc = fmaf(w.w, h4a.w, acc);
                w = *(const float4*)&wh[128 + 4 * lane];
                acc = fmaf(w.x, h4b.x, acc); acc = fmaf(w.y, h4b.y, acc);
                acc = fmaf(w.z, h4b.z, acc); acc = fmaf(w.w, h4b.w, acc);
                {   float2 w2 = *(const float2*)&wh[256 + 2 * lane];
                    acc = fmaf(w2.x, h2.x, acc); acc = fmaf(w2.y, h2.y, acc); }
                #pragma unroll
                for (int o = 16; o > 0; o >>= 1) acc += __shfl_down_sync(0xffffffffu, acc, o);
                if (lane == 0) sh_g[r] = acc + b1[r];
            }
        }
        __syncthreads();

        // ---- P4: LSTM1 nonlinearity -> g = h1p ----
        if (tid < PRED) {
            float gi = sh_g[tid], gf = sh_g[PRED + tid], gg = sh_g[2 * PRED + tid], go = sh_g[3 * PRED + tid];
            float c = sigf(gf) * sh_c1[tid] + sigf(gi) * tanhf(gg);
            sh_c1p[tid] = c;
            sh_h1p[tid] = sigf(go) * tanhf(c);
        }
        __syncthreads();

        // ---- P5: joint hidden = relu([f,g] @ Wj1^T + bj1)  (512 rows, 16/warp) ----
        {
            float4 z4[10];
            #pragma unroll
            for (int j = 0; j < 8; ++j) z4[j] = *(const float4*)&sh_f[128 * j + 4 * lane];
            z4[8] = *(const float4*)&sh_h1p[4 * lane];
            z4[9] = *(const float4*)&sh_h1p[128 + 4 * lane];
            float2 z2 = *(const float2*)&sh_h1p[256 + 2 * lane];
            int rbase = warp * 16;
            for (int rr = 0; rr < 16; ++rr) {
                int r = rbase + rr;
                const float* wj = Wj1 + r * ZDIM;
                float acc = 0.f;
                #pragma unroll
                for (int j = 0; j < 10; ++j) {
                    float4 w = *(const float4*)&wj[128 * j + 4 * lane];
                    acc = fmaf(w.x, z4[j].x, acc); acc = fmaf(w.y, z4[j].y, acc);
                    acc = fmaf(w.z, z4[j].z, acc); acc = fmaf(w.w, z4[j].w, acc);
                }
                {   float2 w2 = *(const float2*)&wj[1280 + 2 * lane];
                    acc = fmaf(w2.x, z2.x, acc); acc = fmaf(w2.y, z2.y, acc); }
                #pragma unroll
                for (int o = 16; o > 0; o >>= 1) acc += __shfl_down_sync(0xffffffffu, acc, o);
                if (lane == 0) { float v = acc + bj1[r]; sh_hid[r] = v > 0.f ? v : 0.f; }
            }
        }
        __syncthreads();

        // ---- P6: logits (29 rows, one warp each) ----
        if (warp < VOCAB) {
            const float* w2p = Wj2 + warp * JH;
            float acc = 0.f;
            #pragma unroll
            for (int j = 0; j < 4; ++j) {
                float4 w = *(const float4*)&w2p[128 * j + 4 * lane];
                float4 h = *(const float4*)&sh_hid[128 * j + 4 * lane];
                acc = fmaf(w.x, h.x, acc); acc = fmaf(w.y, h.y, acc);
                acc = fmaf(w.z, h.z, acc); acc = fmaf(w.w, h.w, acc);
            }
            #pragma unroll
            for (int o = 16; o > 0; o >>= 1) acc += __shfl_down_sync(0xffffffffu, acc, o);
            if (lane == 0) sh_logit[warp] = acc + bj2[warp];
        }
        __syncthreads();

        // ---- P7: argmax + control (single thread, matches jnp.argmax first-max) ----
        if (tid == 0) {
            float best = sh_logit[0]; int k = 0;
            #pragma unroll
            for (int v = 1; v < VOCAB; ++v) {
                float lv = sh_logit[v];
                if (lv > best) { best = lv; k = v; }
            }
            int ti = s_ti, sa = s_sa, lc = s_lc;
            bool blk = (k == BLANK);
            if (blk) ti += 1;
            bool done = (ti >= olen);
            if (blk) sa = 0;
            bool nb = !(done || blk);
            if (nb) {
                lc += 1;
                if (lc <= NSTEPS - 1) {                 // JAX scatter: OOB update dropped
                    sh_lt[lc] += (k + 1);
                }
                sa += 1;
            }
            // last label for next step = lt[rows, lc] (gather -> clamp)
            {
                int pos = lc; if (pos > NSTEPS - 1) pos = NSTEPS - 1;
                s_last = sh_lt[pos];
            }
            if (sa >= MAXSYM) { ti += 1; sa = 0; }
            s_ti = ti; s_sa = sa; s_lc = lc; s_nb = nb ? 1 : 0;
        }
        __syncthreads();

        // ---- P8: conditional state commit ----
        if (s_nb && tid < PRED) {
            sh_h0[tid] = sh_h0p[tid]; sh_c0[tid] = sh_c0p[tid];
            sh_h1[tid] = sh_h1p[tid]; sh_c1[tid] = sh_c1p[tid];
        }
        __syncthreads();
    }

    // ---- Output as FLOAT32 (harness __output__ dtype): lt then lc ----
    for (int i = tid; i < NSTEPS; i += 1024)
        d_out[b * NSTEPS + i] = (float)sh_lt[i];
    if (tid == 0 && write_lc)
        d_out[BATCH * NSTEPS + b] = (float)s_lc;
}

extern "C" void kernel_launch(void* const* d_in, const int* in_sizes, int n_in,
                              void* d_out, int out_size) {
    const float* x        = (const float*)d_in[0];
    const int*   out_lens = (const int*)  d_in[1];
    const float* emb      = (const float*)d_in[2];
    const float* Wi0      = (const float*)d_in[3];
    const float* Wh0      = (const float*)d_in[4];
    const float* b0       = (const float*)d_in[5];
    const float* Wi1      = (const float*)d_in[6];
    const float* Wh1      = (const float*)d_in[7];
    const float* b1       = (const float*)d_in[8];
    const float* Wj1      = (const float*)d_in[9];
    const float* bj1      = (const float*)d_in[10];
    const float* Wj2      = (const float*)d_in[11];
    const float* bj2      = (const float*)d_in[12];

    int write_lc = (out_size >= BATCH * NSTEPS + BATCH) ? 1 : 0;

    rnnt_greedy_kernel<<<BATCH, 1024>>>(x, out_lens, emb,
                                        Wi0, Wh0, b0, Wi1, Wh1, b1,
                                        Wj1, bj1, Wj2, bj2,
                                        (float*)d_out, write_lc);
}

// round 5
// speedup vs baseline: 1.5887x; 1.5887x over previous
#include <cuda_runtime.h>
#include <math.h>
#include <stdint.h>

#define ENC 1024
#define PRED 320
#define JH 512
#define VOCAB 29
#define BLANK 28
#define MAXSYM 6
#define BATCH 32
#define TLEN 48
#define NSTEPS 288
#define ZDIM 1344
#define CSIZE 4                    // CTAs per cluster
#define MB 2                       // batch rows per cluster
#define NTHREADS 512
#define UNITS_PER (PRED / CSIZE)   // 80 LSTM units per CTA
#define GROWS_PER (4 * UNITS_PER)  // 320 gate rows per CTA
#define JROWS_PER (JH / CSIZE)     // 128 joint rows per CTA

#define CLUSTER_SYNC() do { \
    asm volatile("barrier.cluster.arrive.aligned;" ::: "memory"); \
    asm volatile("barrier.cluster.wait.aligned;"   ::: "memory"); \
} while (0)

__device__ __forceinline__ float sigf(float v) { return 1.0f / (1.0f + expf(-v)); }

__device__ __forceinline__ float wredsum(float v) {
    #pragma unroll
    for (int o = 16; o > 0; o >>= 1) v += __shfl_down_sync(0xffffffffu, v, o);
    return v;
}

__device__ __forceinline__ uint32_t s2u(const void* p) {
    return (uint32_t)__cvta_generic_to_shared((void*)p);
}

// store v into the SMEM copy of `addr` in cluster CTA `rank`
__device__ __forceinline__ void st_peer(uint32_t addr, int rank, float v) {
    uint32_t pa;
    asm volatile("mapa.shared::cluster.u32 %0, %1, %2;" : "=r"(pa) : "r"(addr), "r"(rank));
    asm volatile("st.shared::cluster.f32 [%0], %1;" :: "r"(pa), "f"(v));
}

// Gate GEMV: 320 local rows (4 gates x 80 units), width 640 = [A(320);B(320)], 2 batch rows fused.
// lanes 0-15 cover A cols [20*lane, +20); lanes 16-31 cover B cols [20*(lane-16), +20).
__device__ __forceinline__ void gemv_gates(
    const float* __restrict__ Wi, const float* __restrict__ Wh, const float* __restrict__ bias,
    const float* sA0, const float* sA1,   // width-320 part A for m=0,1 (multiplies Wi)
    const float* sB0, const float* sB1,   // width-320 part B for m=0,1 (multiplies Wh)
    float* g0, float* g1,                 // gate outputs [320] per m, index = gate*80 + lu
    int rank, int warp, int lane)
{
    const int  colbase = 20 * (lane & 15);
    const bool loA = (lane < 16);
    const float* a0 = (loA ? sA0 : sB0) + colbase;
    const float* a1 = (loA ? sA1 : sB1) + colbase;
    float4 v0[5], v1[5];
    #pragma unroll
    for (int j = 0; j < 5; ++j) {
        v0[j] = *(const float4*)(a0 + 4 * j);
        v1[j] = *(const float4*)(a1 + 4 * j);
    }
    const float* Wsel = loA ? Wi : Wh;
    for (int rr = 0; rr < 20; ++rr) {
        int r  = warp * 20 + rr;          // [0, 320)
        int g  = r / UNITS_PER;           // gate 0..3 (i,f,g,o)
        int lu = r - g * UNITS_PER;       // local unit
        int grow = g * PRED + rank * UNITS_PER + lu;   // global weight row
        const float* w = Wsel + grow * PRED + colbase;
        float acc0 = 0.f, acc1 = 0.f;
        #pragma unroll
        for (int j = 0; j < 5; ++j) {
            float4 wv = *(const float4*)(w + 4 * j);
            acc0 = fmaf(wv.x, v0[j].x, acc0); acc0 = fmaf(wv.y, v0[j].y, acc0);
            acc0 = fmaf(wv.z, v0[j].z, acc0); acc0 = fmaf(wv.w, v0[j].w, acc0);
            acc1 = fmaf(wv.x, v1[j].x, acc1); acc1 = fmaf(wv.y, v1[j].y, acc1);
            acc1 = fmaf(wv.z, v1[j].z, acc1); acc1 = fmaf(wv.w, v1[j].w, acc1);
        }
        acc0 = wredsum(acc0);
        acc1 = wredsum(acc1);
        if (lane == 0) {
            float bb = bias[grow];
            g0[r] = acc0 + bb;
            g1[r] = acc1 + bb;
        }
    }
}

__global__ __launch_bounds__(NTHREADS, 1) __cluster_dims__(CSIZE, 1, 1)
void rnnt_greedy_kernel(const float* __restrict__ x,
                        const int*   __restrict__ out_lens,
                        const float* __restrict__ emb,
                        const float* __restrict__ Wi0, const float* __restrict__ Wh0, const float* __restrict__ b0,
                        const float* __restrict__ Wi1, const float* __restrict__ Wh1, const float* __restrict__ b1,
                        const float* __restrict__ Wj1, const float* __restrict__ bj1,
                        const float* __restrict__ Wj2, const float* __restrict__ bj2,
                        float* __restrict__ d_out, int write_lc)
{
    const int tid  = threadIdx.x;
    const int lane = tid & 31;
    const int warp = tid >> 5;

    uint32_t rank;
    asm("mov.u32 %0, %%cluster_ctarank;" : "=r"(rank));
    const int cid   = blockIdx.x / CSIZE;
    const int bbase = cid * MB;

    __shared__ __align__(16) float sh_f[MB][ENC];
    __shared__ __align__(16) float sh_e[MB][PRED];
    __shared__ __align__(16) float sh_h0[MB][PRED],  sh_h1[MB][PRED];
    __shared__ __align__(16) float sh_h0p[MB][PRED], sh_h1p[MB][PRED];
    __shared__ __align__(16) float sh_c0[MB][PRED],  sh_c1[MB][PRED];
    __shared__ __align__(16) float sh_c0p[MB][PRED], sh_c1p[MB][PRED];
    __shared__ __align__(16) float sh_g[MB][GROWS_PER];
    __shared__ __align__(16) float sh_hid[MB][JH];
    __shared__ __align__(16) float sh_logit[MB][32];
    __shared__ int sh_lt[MB][NSTEPS];
    __shared__ int s_last[MB], s_lc[MB], s_ti[MB], s_sa[MB], s_nb[MB], s_olen[MB];

    // ---- init ----
    for (int i = tid; i < MB * PRED; i += NTHREADS) {
        int m = i / PRED, j = i - m * PRED;
        sh_h0[m][j] = 0.f; sh_h1[m][j] = 0.f;
        sh_c0[m][j] = 0.f; sh_c1[m][j] = 0.f;
    }
    for (int i = tid; i < MB * NSTEPS; i += NTHREADS) {
        int m = i / NSTEPS, j = i - m * NSTEPS;
        sh_lt[m][j] = -1;
    }
    if (tid == 0) {
        #pragma unroll
        for (int m = 0; m < MB; ++m) {
            s_last[m] = -1; s_lc[m] = 0; s_ti[m] = 0; s_sa[m] = 0; s_nb[m] = 0;
            s_olen[m] = out_lens[bbase + m];
        }
    }
    __syncthreads();
    CLUSTER_SYNC();

    for (int step = 0; step < NSTEPS; ++step) {
        // ---- P0: encoder frames + embeddings (replicated per CTA) ----
        for (int i = tid; i < MB * ENC; i += NTHREADS) {
            int m = i >> 10, col = i & (ENC - 1);
            int fi = s_ti[m]; if (fi > TLEN - 1) fi = TLEN - 1;
            sh_f[m][col] = x[((bbase + m) * TLEN + fi) * ENC + col];
        }
        for (int i = tid; i < MB * PRED; i += NTHREADS) {
            int m = i / PRED, col = i - m * PRED;
            int lab = s_last[m];
            int labc = lab > (VOCAB - 2) ? (VOCAB - 2) : lab;
            sh_e[m][col] = (lab >= 0) ? emb[labc * PRED + col] : 0.0f;
        }
        __syncthreads();

        // ---- P1: layer-0 gates (this CTA's 80 units x 4 gates, both batch rows) ----
        gemv_gates(Wi0, Wh0, b0, sh_e[0], sh_e[1], sh_h0[0], sh_h0[1],
                   sh_g[0], sh_g[1], (int)rank, warp, lane);
        __syncthreads();

        // ---- P2: LSTM0 nonlinearity for local slice; broadcast h0p slice to all CTAs ----
        if (tid < MB * UNITS_PER) {
            int m  = tid / UNITS_PER, lu = tid - m * UNITS_PER;
            int gu = rank * UNITS_PER + lu;
            float gi = sh_g[m][lu], gf = sh_g[m][UNITS_PER + lu];
            float gg = sh_g[m][2 * UNITS_PER + lu], go = sh_g[m][3 * UNITS_PER + lu];
            float c  = sigf(gf) * sh_c0[m][gu] + sigf(gi) * tanhf(gg);
            sh_c0p[m][gu] = c;
            float h  = sigf(go) * tanhf(c);
            uint32_t a = s2u(&sh_h0p[m][gu]);
            #pragma unroll
            for (int rk = 0; rk < CSIZE; ++rk) st_peer(a, rk, h);
        }
        CLUSTER_SYNC();   // S1: full h0p assembled everywhere

        // ---- P3: layer-1 gates ----
        gemv_gates(Wi1, Wh1, b1, sh_h0p[0], sh_h0p[1], sh_h1[0], sh_h1[1],
                   sh_g[0], sh_g[1], (int)rank, warp, lane);
        __syncthreads();

        // ---- P4: LSTM1 nonlinearity; broadcast h1p slice ----
        if (tid < MB * UNITS_PER) {
            int m  = tid / UNITS_PER, lu = tid - m * UNITS_PER;
            int gu = rank * UNITS_PER + lu;
            float gi = sh_g[m][lu], gf = sh_g[m][UNITS_PER + lu];
            float gg = sh_g[m][2 * UNITS_PER + lu], go = sh_g[m][3 * UNITS_PER + lu];
            float c  = sigf(gf) * sh_c1[m][gu] + sigf(gi) * tanhf(gg);
            sh_c1p[m][gu] = c;
            float h  = sigf(go) * tanhf(c);
            uint32_t a = s2u(&sh_h1p[m][gu]);
            #pragma unroll
            for (int rk = 0; rk < CSIZE; ++rk) st_peer(a, rk, h);
        }
        CLUSTER_SYNC();   // S2: full h1p assembled everywhere

        // ---- P5: joint hidden (this CTA's 128 rows, both batch rows) ----
        {
            float acc[8][2];
            #pragma unroll
            for (int rr = 0; rr < 8; ++rr) { acc[rr][0] = 0.f; acc[rr][1] = 0.f; }

            // f part: 2 passes of 512 cols (16 cols/lane each)
            #pragma unroll
            for (int pass = 0; pass < 2; ++pass) {
                float4 a0[4], a1[4];
                const float* f0 = &sh_f[0][pass * 512 + 16 * lane];
                const float* f1 = &sh_f[1][pass * 512 + 16 * lane];
                #pragma unroll
                for (int j = 0; j < 4; ++j) {
                    a0[j] = *(const float4*)(f0 + 4 * j);
                    a1[j] = *(const float4*)(f1 + 4 * j);
                }
                #pragma unroll
                for (int rr = 0; rr < 8; ++rr) {
                    int jrow = rank * JROWS_PER + warp * 8 + rr;
                    const float* w = Wj1 + jrow * ZDIM + pass * 512 + 16 * lane;
                    float s0 = acc[rr][0], s1 = acc[rr][1];
                    #pragma unroll
                    for (int j = 0; j < 4; ++j) {
                        float4 wv = *(const float4*)(w + 4 * j);
                        s0 = fmaf(wv.x, a0[j].x, s0); s0 = fmaf(wv.y, a0[j].y, s0);
                        s0 = fmaf(wv.z, a0[j].z, s0); s0 = fmaf(wv.w, a0[j].w, s0);
                        s1 = fmaf(wv.x, a1[j].x, s1); s1 = fmaf(wv.y, a1[j].y, s1);
                        s1 = fmaf(wv.z, a1[j].z, s1); s1 = fmaf(wv.w, a1[j].w, s1);
                    }
                    acc[rr][0] = s0; acc[rr][1] = s1;
                }
            }
            // g part: h1p, 320 cols (10 cols/lane as 5 x float2)
            {
                float2 a0[5], a1[5];
                const float* p0 = &sh_h1p[0][10 * lane];
                const float* p1 = &sh_h1p[1][10 * lane];
                #pragma unroll
                for (int j = 0; j < 5; ++j) {
                    a0[j] = *(const float2*)(p0 + 2 * j);
                    a1[j] = *(const float2*)(p1 + 2 * j);
                }
                #pragma unroll
                for (int rr = 0; rr < 8; ++rr) {
                    int jrow = rank * JROWS_PER + warp * 8 + rr;
                    const float* w = Wj1 + jrow * ZDIM + ENC + 10 * lane;
                    float s0 = acc[rr][0], s1 = acc[rr][1];
                    #pragma unroll
                    for (int j = 0; j < 5; ++j) {
                        float2 wv = *(const float2*)(w + 2 * j);
                        s0 = fmaf(wv.x, a0[j].x, s0); s0 = fmaf(wv.y, a0[j].y, s0);
                        s1 = fmaf(wv.x, a1[j].x, s1); s1 = fmaf(wv.y, a1[j].y, s1);
                    }
                    acc[rr][0] = s0; acc[rr][1] = s1;
                }
            }
            #pragma unroll
            for (int rr = 0; rr < 8; ++rr) {
                int jrow = rank * JROWS_PER + warp * 8 + rr;
                float r0 = wredsum(acc[rr][0]);
                float r1 = wredsum(acc[rr][1]);
                if (lane == 0) {
                    float bb = bj1[jrow];
                    float v0 = r0 + bb; v0 = v0 > 0.f ? v0 : 0.f;
                    float v1 = r1 + bb; v1 = v1 > 0.f ? v1 : 0.f;
                    uint32_t ad0 = s2u(&sh_hid[0][jrow]);
                    uint32_t ad1 = s2u(&sh_hid[1][jrow]);
                    #pragma unroll
                    for (int rk = 0; rk < CSIZE; ++rk) {
                        st_peer(ad0, rk, v0);
                        st_peer(ad1, rk, v1);
                    }
                }
            }
        }
        CLUSTER_SYNC();   // S3: full hid assembled everywhere

        // ---- P6: logits (replicated: every CTA computes all 29 x 2) ----
        for (int v = warp; v < VOCAB; v += 16) {
            const float* w = Wj2 + v * JH + 16 * lane;
            float4 wv[4];
            #pragma unroll
            for (int j = 0; j < 4; ++j) wv[j] = *(const float4*)(w + 4 * j);
            float acc0 = 0.f, acc1 = 0.f;
            #pragma unroll
            for (int j = 0; j < 4; ++j) {
                float4 h0v = *(const float4*)&sh_hid[0][16 * lane + 4 * j];
                float4 h1v = *(const float4*)&sh_hid[1][16 * lane + 4 * j];
                acc0 = fmaf(wv[j].x, h0v.x, acc0); acc0 = fmaf(wv[j].y, h0v.y, acc0);
                acc0 = fmaf(wv[j].z, h0v.z, acc0); acc0 = fmaf(wv[j].w, h0v.w, acc0);
                acc1 = fmaf(wv[j].x, h1v.x, acc1); acc1 = fmaf(wv[j].y, h1v.y, acc1);
                acc1 = fmaf(wv[j].z, h1v.z, acc1); acc1 = fmaf(wv[j].w, h1v.w, acc1);
            }
            acc0 = wredsum(acc0);
            acc1 = wredsum(acc1);
            if (lane == 0) {
                float bb = bj2[v];
                sh_logit[0][v] = acc0 + bb;
                sh_logit[1][v] = acc1 + bb;
            }
        }
        __syncthreads();

        // ---- P7: argmax + control, replicated identically in every CTA ----
        if (tid == 0) {
            #pragma unroll
            for (int m = 0; m < MB; ++m) {
                float best = sh_logit[m][0]; int k = 0;
                #pragma unroll
                for (int v = 1; v < VOCAB; ++v) {
                    float lv = sh_logit[m][v];
                    if (lv > best) { best = lv; k = v; }
                }
                int ti = s_ti[m], sa = s_sa[m], lc = s_lc[m];
                bool blk = (k == BLANK);
                if (blk) ti += 1;
                bool done = (ti >= s_olen[m]);
                if (blk) sa = 0;
                bool nb = !(done || blk);
                if (nb) {
                    lc += 1;
                    if (lc <= NSTEPS - 1) sh_lt[m][lc] += (k + 1);  // JAX scatter: OOB dropped
                    sa += 1;
                }
                {
                    int pos = lc; if (pos > NSTEPS - 1) pos = NSTEPS - 1;
                    s_last[m] = sh_lt[m][pos];                       // JAX gather: clamp
                }
                if (sa >= MAXSYM) { ti += 1; sa = 0; }
                s_ti[m] = ti; s_sa[m] = sa; s_lc[m] = lc; s_nb[m] = nb ? 1 : 0;
            }
        }
        __syncthreads();

        // ---- P8: conditional state commit (h full, c local slice) ----
        for (int i = tid; i < MB * PRED; i += NTHREADS) {
            int m = i / PRED, j = i - m * PRED;
            if (s_nb[m]) { sh_h0[m][j] = sh_h0p[m][j]; sh_h1[m][j] = sh_h1p[m][j]; }
        }
        if (tid < MB * UNITS_PER) {
            int m  = tid / UNITS_PER, lu = tid - m * UNITS_PER;
            int gu = rank * UNITS_PER + lu;
            if (s_nb[m]) { sh_c0[m][gu] = sh_c0p[m][gu]; sh_c1[m][gu] = sh_c1p[m][gu]; }
        }
        CLUSTER_SYNC();   // S4: protects h0p against next step's peer writes
    }

    // ---- output (rank 0 of each cluster): lt as float32, then lc ----
    if (rank == 0) {
        for (int m = 0; m < MB; ++m) {
            for (int i = tid; i < NSTEPS; i += NTHREADS)
                d_out[(bbase + m) * NSTEPS + i] = (float)sh_lt[m][i];
        }
        if (tid == 0 && write_lc) {
            d_out[BATCH * NSTEPS + bbase + 0] = (float)s_lc[0];
            d_out[BATCH * NSTEPS + bbase + 1] = (float)s_lc[1];
        }
    }
}

extern "C" void kernel_launch(void* const* d_in, const int* in_sizes, int n_in,
                              void* d_out, int out_size) {
    const float* x        = (const float*)d_in[0];
    const int*   out_lens = (const int*)  d_in[1];
    const float* emb      = (const float*)d_in[2];
    const float* Wi0      = (const float*)d_in[3];
    const float* Wh0      = (const float*)d_in[4];
    const float* b0       = (const float*)d_in[5];
    const float* Wi1      = (const float*)d_in[6];
    const float* Wh1      = (const float*)d_in[7];
    const float* b1       = (const float*)d_in[8];
    const float* Wj1      = (const float*)d_in[9];
    const float* bj1      = (const float*)d_in[10];
    const float* Wj2      = (const float*)d_in[11];
    const float* bj2      = (const float*)d_in[12];

    int write_lc = (out_size >= BATCH * NSTEPS + BATCH) ? 1 : 0;

    rnnt_greedy_kernel<<<(BATCH / MB) * CSIZE, NTHREADS>>>(
        x, out_lens, emb,
        Wi0, Wh0, b0, Wi1, Wh1, b1,
        Wj1, bj1, Wj2, bj2,
        (float*)d_out, write_lc);
}